// round 15
// baseline (speedup 1.0000x reference)
#include <cuda_runtime.h>
#include <cuda_bf16.h>
#include <math.h>
#include <cstdint>

#define N_NODES 100000
#define N_EDGES 1600000
#define IN_CH   128
#define HID     128
#define OUT_CH  64

#define SCAN_NBLK ((N_NODES + 255) / 256)   // 391

typedef unsigned long long u64;

// ---------------- scratch (device globals; no allocation allowed) ----------
__device__ __nv_bfloat16 g_hb[(size_t)N_NODES * HID];  // transformed features (bf16)
__device__ float g_agg[(size_t)N_NODES * HID];         // aggregated / activated (fp32)
__device__ float g_dinv[N_NODES];
__device__ int   g_deg[N_NODES];                       // zero at load; re-zeroed each run
__device__ int   g_rowptr[N_NODES + 1];
__device__ int   g_cursor[N_NODES];
__device__ int   g_csr[N_EDGES];
__device__ int   g_bsum[SCAN_NBLK];
__device__ int   g_boff[SCAN_NBLK];
__device__ unsigned int g_min[OUT_CH];

// ---------------- float <-> monotone uint key ------------------------------
__device__ __forceinline__ unsigned int fkey(float f) {
    unsigned int u = __float_as_uint(f);
    return (u & 0x80000000u) ? ~u : (u | 0x80000000u);
}
__device__ __forceinline__ float funkey(unsigned int k) {
    unsigned int u = (k & 0x80000000u) ? (k ^ 0x80000000u) : ~k;
    return __uint_as_float(u);
}

__device__ __forceinline__ uint32_t smem_u32(const void* p) {
    uint32_t a;
    asm("{ .reg .u64 t; cvta.to.shared.u64 t, %1; cvt.u32.u64 %0, t; }"
        : "=r"(a) : "l"(p));
    return a;
}

// ---------------- packed f32x2 helpers (sm_10x FFMA2/FADD2 via PTX) ---------
__device__ __forceinline__ u64 pack2(uint32_t lo, uint32_t hi) {
    u64 r;
    asm("mov.b64 %0, {%1, %2};" : "=l"(r) : "r"(lo), "r"(hi));
    return r;
}
__device__ __forceinline__ void unpk2(u64 v, float& a, float& b) {
    uint32_t x, y;
    asm("mov.b64 {%0, %1}, %2;" : "=r"(x), "=r"(y) : "l"(v));
    a = __uint_as_float(x);
    b = __uint_as_float(y);
}
__device__ __forceinline__ u64 add2(u64 a, u64 b) {
    u64 r;
    asm("add.rn.f32x2 %0, %1, %2;" : "=l"(r) : "l"(a), "l"(b));
    return r;
}
__device__ __forceinline__ u64 mul2(u64 a, u64 b) {
    u64 r;
    asm("mul.rn.f32x2 %0, %1, %2;" : "=l"(r) : "l"(a), "l"(b));
    return r;
}
__device__ __forceinline__ u64 fma2(u64 a, u64 b, u64 c) {
    u64 r;
    asm("fma.rn.f32x2 %0, %1, %2, %3;" : "=l"(r) : "l"(a), "l"(b), "l"(c));
    return r;
}
__device__ __forceinline__ u64 bcast2(float f) {
    uint32_t u = __float_as_uint(f);
    return pack2(u, u);
}
// bf16x2 word -> packed f32x2 (exact widening: 2 ALU ops, pair-allocated)
__device__ __forceinline__ void bf2pairs(uint4 v, u64* p) {
    p[0] = pack2(v.x << 16, v.x & 0xFFFF0000u);
    p[1] = pack2(v.y << 16, v.y & 0xFFFF0000u);
    p[2] = pack2(v.z << 16, v.z & 0xFFFF0000u);
    p[3] = pack2(v.w << 16, v.w & 0xFFFF0000u);
}

// ---------------- CSR build ------------------------------------------------
__global__ void count_deg_kernel(const int* __restrict__ ei) {
    int e4 = (blockIdx.x * blockDim.x + threadIdx.x) * 4;
    if (e4 < N_EDGES) {
        int4 d = *reinterpret_cast<const int4*>(&ei[N_EDGES + e4]);
        atomicAdd(&g_deg[d.x], 1);
        atomicAdd(&g_deg[d.y], 1);
        atomicAdd(&g_deg[d.z], 1);
        atomicAdd(&g_deg[d.w], 1);
    }
}

__global__ void scan_pass1() {
    int i = blockIdx.x * 256 + threadIdx.x;
    int d = (i < N_NODES) ? g_deg[i] : 0;
    __shared__ int sm[256];
    sm[threadIdx.x] = d;
    __syncthreads();
#pragma unroll
    for (int o = 128; o > 0; o >>= 1) {
        if (threadIdx.x < o) sm[threadIdx.x] += sm[threadIdx.x + o];
        __syncthreads();
    }
    if (threadIdx.x == 0) g_bsum[blockIdx.x] = sm[0];
}

__global__ void scan_pass2() {
    __shared__ int sm[512];
    int t = threadIdx.x;
    if (t < OUT_CH) g_min[t] = 0xFFFFFFFFu;   // init fused-pool accumulator
    sm[t] = (t < SCAN_NBLK) ? g_bsum[t] : 0;
    __syncthreads();
    for (int o = 1; o < 512; o <<= 1) {
        int v = (t >= o) ? sm[t - o] : 0;
        __syncthreads();
        sm[t] += v;
        __syncthreads();
    }
    if (t < SCAN_NBLK) g_boff[t] = (t == 0) ? 0 : sm[t - 1];
    if (t == 511) g_rowptr[N_NODES] = sm[SCAN_NBLK - 1];
}

__global__ void scan_pass3() {
    int i = blockIdx.x * 256 + threadIdx.x;
    int d = (i < N_NODES) ? g_deg[i] : 0;
    __shared__ int sm[256];
    int t = threadIdx.x;
    sm[t] = d;
    __syncthreads();
    for (int o = 1; o < 256; o <<= 1) {
        int v = (t >= o) ? sm[t - o] : 0;
        __syncthreads();
        sm[t] += v;
        __syncthreads();
    }
    if (i < N_NODES) {
        int excl = g_boff[blockIdx.x] + sm[t] - d;
        g_rowptr[i] = excl;
        g_cursor[i] = excl;
        g_dinv[i] = rsqrtf((float)(d + 1));  // +1 self-loop
        g_deg[i] = 0;                        // restore zero invariant for next run
    }
}

__global__ void fill_csr_kernel(const int* __restrict__ ei) {
    int e4 = (blockIdx.x * blockDim.x + threadIdx.x) * 4;
    if (e4 < N_EDGES) {
        int4 s = *reinterpret_cast<const int4*>(&ei[e4]);
        int4 d = *reinterpret_cast<const int4*>(&ei[N_EDGES + e4]);
        g_csr[atomicAdd(&g_cursor[d.x], 1)] = s.x;
        g_csr[atomicAdd(&g_cursor[d.y], 1)] = s.y;
        g_csr[atomicAdd(&g_cursor[d.z], 1)] = s.z;
        g_csr[atomicAdd(&g_cursor[d.w], 1)] = s.w;
    }
}

// ---------------- tf32 mma helpers ------------------------------------------
__device__ __forceinline__ uint32_t f2tf32(float f) {
    uint32_t u;
    asm("cvt.rna.tf32.f32 %0, %1;" : "=r"(u) : "f"(f));
    return u;
}

__device__ __forceinline__ void mma_tf32(float* c, const uint32_t* a, const uint32_t* b) {
    asm volatile(
        "mma.sync.aligned.m16n8k8.row.col.f32.tf32.tf32.f32 "
        "{%0,%1,%2,%3}, {%4,%5,%6,%7}, {%8,%9}, {%0,%1,%2,%3};"
        : "+f"(c[0]), "+f"(c[1]), "+f"(c[2]), "+f"(c[3])
        : "r"(a[0]), "r"(a[1]), "r"(a[2]), "r"(a[3]), "r"(b[0]), "r"(b[1]));
}

// ---------------- persistent tensor-core GEMM (512 threads) ------------------
// outh[m][n] = bf16( scale(m) * (A @ W)[m][n] ), scale = g_dinv[m] if SCALE
// W resident in smem; A tiles (128x128 fp32) cp.async double-buffered.
// 16 warps: 4(M) x 4(N); warp tile 32M x (BN/4)N; cvt.rna in-register after LDS.
template <int BN, bool SCALE>
__global__ void __launch_bounds__(512, 1)
gemm_persist_kernel(const float* __restrict__ A, const float* __restrict__ W,
                    __nv_bfloat16* __restrict__ outh, int M) {
    constexpr int PA = 132;          // raw fp32 A tile pitch (conflict-free frags)
    constexpr int PB = BN + 8;       // PB % 32 == 8 -> conflict-free B frags
    constexpr int TN = BN / 32;      // n8-tiles per warp: 4 (BN=128) or 2 (BN=64)
    const int ntiles = (M + 127) >> 7;

    extern __shared__ uint32_t smem[];
    uint32_t* Ws = smem;                                  // [128][PB] tf32
    float* Ab0 = reinterpret_cast<float*>(smem + 128 * PB);   // [128][PA] raw
    float* Ab1 = Ab0 + 128 * PA;

    const int tid = threadIdx.x;
    const int lane = tid & 31;
    const int wid = tid >> 5;
    const int wm = (wid & 3) * 32;          // 4 M-groups
    const int wn = (wid >> 2) * (BN / 4);   // 4 N-groups
    const int ar = lane >> 2;
    const int ak = lane & 3;
    const int bn = wn + ar;

    // ---- load W once (tf32-rounded) ----
    for (int i = tid; i < 128 * (BN / 4); i += 512) {
        int r = i / (BN / 4);
        int c4 = (i % (BN / 4)) * 4;
        float4 v = *reinterpret_cast<const float4*>(&W[(size_t)r * BN + c4]);
        uint4 u;
        u.x = f2tf32(v.x); u.y = f2tf32(v.y); u.z = f2tf32(v.z); u.w = f2tf32(v.w);
        *reinterpret_cast<uint4*>(&Ws[r * PB + c4]) = u;
    }

    const uint32_t ab_addr0 = smem_u32(Ab0);
    const uint32_t ab_addr1 = smem_u32(Ab1);

    auto issue_copy = [&](int buf, int tile) {
        const uint32_t base = buf ? ab_addr1 : ab_addr0;
        const int m0 = tile << 7;
#pragma unroll
        for (int t = 0; t < 8; t++) {
            int i = tid + t * 512;          // float4 index, 4096 total
            int r = i >> 5;
            int c4 = (i & 31) * 4;
            int row = m0 + r;
            uint32_t dst = base + (uint32_t)(r * PA + c4) * 4u;
            const float* src = &A[(size_t)(row < M ? row : 0) * 128 + c4];
            int sz = (row < M) ? 16 : 0;    // zero-fill OOB rows
            asm volatile("cp.async.cg.shared.global [%0], [%1], 16, %2;"
                         :: "r"(dst), "l"(src), "r"(sz) : "memory");
        }
        asm volatile("cp.async.commit_group;" ::: "memory");
    };

    int tile = blockIdx.x;
    int cur = 0;
    if (tile < ntiles) issue_copy(0, tile);

    for (; tile < ntiles; tile += gridDim.x) {
        const int next = tile + gridDim.x;
        asm volatile("cp.async.wait_group 0;" ::: "memory");
        __syncthreads();                     // buf[cur] ready; prev compute done
        if (next < ntiles) issue_copy(cur ^ 1, next);   // overlaps compute below

        const float* as = cur ? Ab1 : Ab0;
        float acc[2][TN][4] = {};

#pragma unroll
        for (int k0 = 0; k0 < 128; k0 += 8) {
            uint32_t a[2][4];
#pragma unroll
            for (int mi = 0; mi < 2; mi++) {
                int r = wm + mi * 16 + ar;
                a[mi][0] = f2tf32(as[r * PA + k0 + ak]);
                a[mi][1] = f2tf32(as[(r + 8) * PA + k0 + ak]);
                a[mi][2] = f2tf32(as[r * PA + k0 + ak + 4]);
                a[mi][3] = f2tf32(as[(r + 8) * PA + k0 + ak + 4]);
            }
            uint32_t b[TN][2];
#pragma unroll
            for (int ni = 0; ni < TN; ni++) {
                b[ni][0] = Ws[(k0 + ak) * PB + bn + ni * 8];
                b[ni][1] = Ws[(k0 + ak + 4) * PB + bn + ni * 8];
            }
#pragma unroll
            for (int mi = 0; mi < 2; mi++)
#pragma unroll
                for (int ni = 0; ni < TN; ni++)
                    mma_tf32(acc[mi][ni], a[mi], b[ni]);
        }

        // ---- epilogue: scale, pack bf16x2, store ----
        const int m0t = tile << 7;
#pragma unroll
        for (int mi = 0; mi < 2; mi++) {
            int r0 = m0t + wm + mi * 16 + ar;
            int r1 = r0 + 8;
            float d0 = 1.f, d1 = 1.f;
            if (SCALE) {
                if (r0 < M) d0 = g_dinv[r0];
                if (r1 < M) d1 = g_dinv[r1];
            }
#pragma unroll
            for (int ni = 0; ni < TN; ni++) {
                int col = wn + ni * 8 + ak * 2;
                if (r0 < M) {
                    __nv_bfloat162 v0 =
                        __floats2bfloat162_rn(acc[mi][ni][0] * d0, acc[mi][ni][1] * d0);
                    *reinterpret_cast<__nv_bfloat162*>(&outh[(size_t)r0 * BN + col]) = v0;
                }
                if (r1 < M) {
                    __nv_bfloat162 v1 =
                        __floats2bfloat162_rn(acc[mi][ni][2] * d1, acc[mi][ni][3] * d1);
                    *reinterpret_cast<__nv_bfloat162*>(&outh[(size_t)r1 * BN + col]) = v1;
                }
            }
        }
        cur ^= 1;
    }
}

// ---------------- SpMM C=128: warp/node, half-warp/edge, f32x2 math ---------
// EDGE_SCALE (layer 1): h unscaled; apply dinv[src] per edge, dinv[gw] on self.
template <bool EDGE_SCALE>
__global__ void spmm128_kernel(const __nv_bfloat16* __restrict__ h,
                               const float* __restrict__ bias,
                               float* __restrict__ out) {
    int gw = (blockIdx.x * blockDim.x + threadIdx.x) >> 5;
    int lane = threadIdx.x & 31;
    if (gw >= N_NODES) return;
    const int half = lane >> 4;
    const int hl = lane & 15;

    int beg = g_rowptr[gw];
    int end = g_rowptr[gw + 1];
    const float dv = g_dinv[gw];
    const u64 dv2 = bcast2(dv);

    u64 acc[4];
    if (half == 0) {  // self loop on half 0
        uint4 v = *reinterpret_cast<const uint4*>(&h[(size_t)gw * 128 + hl * 8]);
        bf2pairs(v, acc);
        if (EDGE_SCALE) {
#pragma unroll
            for (int p = 0; p < 4; p++) acc[p] = mul2(acc[p], dv2);
        }
    } else {
#pragma unroll
        for (int p = 0; p < 4; p++) acc[p] = 0ull;
    }

    int j = beg + half;
    for (; j + 6 < end; j += 8) {   // 4 edge rows in flight per half-warp
        int s0 = g_csr[j];
        int s1 = g_csr[j + 2];
        int s2 = g_csr[j + 4];
        int s3 = g_csr[j + 6];
        uint4 v0 = *reinterpret_cast<const uint4*>(&h[(size_t)s0 * 128 + hl * 8]);
        uint4 v1 = *reinterpret_cast<const uint4*>(&h[(size_t)s1 * 128 + hl * 8]);
        uint4 v2 = *reinterpret_cast<const uint4*>(&h[(size_t)s2 * 128 + hl * 8]);
        uint4 v3 = *reinterpret_cast<const uint4*>(&h[(size_t)s3 * 128 + hl * 8]);
        u64 p0[4], p1[4], p2[4], p3[4];
        bf2pairs(v0, p0); bf2pairs(v1, p1); bf2pairs(v2, p2); bf2pairs(v3, p3);
        if (EDGE_SCALE) {
            u64 w0 = bcast2(g_dinv[s0]);
            u64 w1 = bcast2(g_dinv[s1]);
            u64 w2 = bcast2(g_dinv[s2]);
            u64 w3 = bcast2(g_dinv[s3]);
#pragma unroll
            for (int p = 0; p < 4; p++) {
                acc[p] = fma2(p0[p], w0, acc[p]);
                acc[p] = fma2(p1[p], w1, acc[p]);
                acc[p] = fma2(p2[p], w2, acc[p]);
                acc[p] = fma2(p3[p], w3, acc[p]);
            }
        } else {
#pragma unroll
            for (int p = 0; p < 4; p++)
                acc[p] = add2(acc[p], add2(add2(p0[p], p1[p]), add2(p2[p], p3[p])));
        }
    }
    for (; j < end; j += 2) {
        int s0 = g_csr[j];
        uint4 v0 = *reinterpret_cast<const uint4*>(&h[(size_t)s0 * 128 + hl * 8]);
        u64 p0[4];
        bf2pairs(v0, p0);
        if (EDGE_SCALE) {
            u64 w0 = bcast2(g_dinv[s0]);
#pragma unroll
            for (int p = 0; p < 4; p++) acc[p] = fma2(p0[p], w0, acc[p]);
        } else {
#pragma unroll
            for (int p = 0; p < 4; p++) acc[p] = add2(acc[p], p0[p]);
        }
    }

    // unpack, combine halves, epilogue
    float a[8];
#pragma unroll
    for (int p = 0; p < 4; p++) unpk2(acc[p], a[p * 2], a[p * 2 + 1]);
#pragma unroll
    for (int i = 0; i < 8; i++) a[i] += __shfl_xor_sync(0xFFFFFFFFu, a[i], 16);

    float o[8];
#pragma unroll
    for (int i = 0; i < 8; i++)
        o[i] = fmaxf(a[i] * dv + bias[hl * 8 + i], 0.f);

    float4 v = (half == 0) ? make_float4(o[0], o[1], o[2], o[3])
                           : make_float4(o[4], o[5], o[6], o[7]);
    *reinterpret_cast<float4*>(&out[(size_t)gw * 128 + hl * 8 + half * 4]) = v;
}

// ---------------- SpMM C=64 fused with min pool (quarter-warp, f32x2) -------
__global__ void spmm_pool_kernel(const __nv_bfloat16* __restrict__ h,
                                 const float* __restrict__ bias) {
    __shared__ float spool[8 * 64];

    int wlocal = threadIdx.x >> 5;
    int gw = (blockIdx.x * blockDim.x + threadIdx.x) >> 5;
    int lane = threadIdx.x & 31;
    const int quarter = lane >> 3;
    const int ql = lane & 7;

    float o[8];
    if (gw < N_NODES) {
        int beg = g_rowptr[gw];
        int end = g_rowptr[gw + 1];

        u64 acc[4];
        if (quarter == 0) {  // self loop on quarter 0
            uint4 v = *reinterpret_cast<const uint4*>(&h[(size_t)gw * 64 + ql * 8]);
            bf2pairs(v, acc);
        } else {
#pragma unroll
            for (int p = 0; p < 4; p++) acc[p] = 0ull;
        }

        int j = beg + quarter;
        for (; j + 4 < end; j += 8) {   // 2 edge rows in flight per quarter
            int s0 = g_csr[j];
            int s1 = g_csr[j + 4];
            uint4 v0 = *reinterpret_cast<const uint4*>(&h[(size_t)s0 * 64 + ql * 8]);
            uint4 v1 = *reinterpret_cast<const uint4*>(&h[(size_t)s1 * 64 + ql * 8]);
            u64 p0[4], p1[4];
            bf2pairs(v0, p0);
            bf2pairs(v1, p1);
#pragma unroll
            for (int p = 0; p < 4; p++)
                acc[p] = add2(acc[p], add2(p0[p], p1[p]));
        }
        if (j < end) {
            int s0 = g_csr[j];
            uint4 v0 = *reinterpret_cast<const uint4*>(&h[(size_t)s0 * 64 + ql * 8]);
            u64 p0[4];
            bf2pairs(v0, p0);
#pragma unroll
            for (int p = 0; p < 4; p++) acc[p] = add2(acc[p], p0[p]);
        }

        float a[8];
#pragma unroll
        for (int p = 0; p < 4; p++) unpk2(acc[p], a[p * 2], a[p * 2 + 1]);
#pragma unroll
        for (int i = 0; i < 8; i++) a[i] += __shfl_xor_sync(0xFFFFFFFFu, a[i], 8);
#pragma unroll
        for (int i = 0; i < 8; i++) a[i] += __shfl_xor_sync(0xFFFFFFFFu, a[i], 16);

        float d = g_dinv[gw];
#pragma unroll
        for (int i = 0; i < 8; i++) o[i] = a[i] * d + bias[ql * 8 + i];
    } else {
#pragma unroll
        for (int i = 0; i < 8; i++) o[i] = 3.4028235e38f;
    }

    if (lane < 8) {
#pragma unroll
        for (int i = 0; i < 8; i++) spool[wlocal * 64 + ql * 8 + i] = o[i];
    }
    __syncthreads();

    if (threadIdx.x < 64) {
        float m = spool[threadIdx.x];
#pragma unroll
        for (int w = 1; w < 8; w++) m = fminf(m, spool[w * 64 + threadIdx.x]);
        atomicMin(&g_min[threadIdx.x], fkey(m));
    }
}

__global__ void min_final_kernel(float* __restrict__ out) {
    out[threadIdx.x] = funkey(g_min[threadIdx.x]);
}

// ---------------- launch ----------------------------------------------------
extern "C" void kernel_launch(void* const* d_in, const int* in_sizes, int n_in,
                              void* d_out, int out_size) {
    const float* x  = (const float*)d_in[0];
    const int*   ei = (const int*)  d_in[1];
    const float* W1 = (const float*)d_in[2];
    const float* b1 = (const float*)d_in[3];
    const float* W2 = (const float*)d_in[4];
    const float* b2 = (const float*)d_in[5];
    const float* W3 = (const float*)d_in[6];
    const float* b3 = (const float*)d_in[7];
    float* out = (float*)d_out;

    __nv_bfloat16* h_ptr = nullptr;
    float* agg_ptr = nullptr;
    cudaGetSymbolAddress((void**)&h_ptr, g_hb);
    cudaGetSymbolAddress((void**)&agg_ptr, g_agg);

    const int SMEM_128 = (128 * 136 + 2 * 128 * 132) * 4;  // 204800 (200KB)
    const int SMEM_64  = (128 * 72 + 2 * 128 * 132) * 4;   // 172032 (168KB)
    cudaFuncSetAttribute((const void*)gemm_persist_kernel<128, false>,
                         cudaFuncAttributeMaxDynamicSharedMemorySize, SMEM_128);
    cudaFuncSetAttribute((const void*)gemm_persist_kernel<128, true>,
                         cudaFuncAttributeMaxDynamicSharedMemorySize, SMEM_128);
    cudaFuncSetAttribute((const void*)gemm_persist_kernel<64, true>,
                         cudaFuncAttributeMaxDynamicSharedMemorySize, SMEM_64);

    const int TPB = 256;
    const int GEMM_GRID = 148;   // persistent: 1 CTA/SM
    const int spmm_blocks = (N_NODES * 32 + TPB - 1) / TPB;

    // CSR build front half (g_deg zero: BSS at load, re-zeroed in scan_pass3)
    count_deg_kernel<<<(N_EDGES / 4 + TPB - 1) / TPB, TPB>>>(ei);      // (1)
    scan_pass1<<<SCAN_NBLK, 256>>>();                                  // (2)
    scan_pass2<<<1, 512>>>();                                          // (3)

    // (4) Layer-1 GEMM (scale-free; only needs x, W1) -> ncu profiles this
    gemm_persist_kernel<128, false><<<GEMM_GRID, 512, SMEM_128>>>(x, W1, h_ptr, N_NODES);

    // CSR build back half
    scan_pass3<<<SCAN_NBLK, 256>>>();                                  // (5)
    fill_csr_kernel<<<(N_EDGES / 4 + TPB - 1) / TPB, TPB>>>(ei);       // (6)

    // Layer 1 aggregation (per-edge dinv scaling)
    spmm128_kernel<true><<<spmm_blocks, TPB>>>(h_ptr, b1, agg_ptr);    // (7)

    // Layer 2
    gemm_persist_kernel<128, true><<<GEMM_GRID, 512, SMEM_128>>>(agg_ptr, W2, h_ptr, N_NODES);
    spmm128_kernel<false><<<spmm_blocks, TPB>>>(h_ptr, b2, agg_ptr);

    // Layer 3 (64 ch) fused with min pool
    gemm_persist_kernel<64, true><<<GEMM_GRID, 512, SMEM_64>>>(agg_ptr, W3, h_ptr, N_NODES);
    spmm_pool_kernel<<<spmm_blocks, TPB>>>(h_ptr, b3);

    min_final_kernel<<<1, 64>>>(out);
}

// round 16
// speedup vs baseline: 1.0273x; 1.0273x over previous
#include <cuda_runtime.h>
#include <cuda_bf16.h>
#include <math.h>
#include <cstdint>

#define N_NODES 100000
#define N_EDGES 1600000
#define IN_CH   128
#define HID     128
#define OUT_CH  64

#define SCAN_NBLK ((N_NODES + 255) / 256)   // 391

// ---------------- scratch (device globals; no allocation allowed) ----------
__device__ __nv_bfloat16 g_hb[(size_t)N_NODES * HID];  // transformed features (bf16)
__device__ float g_agg[(size_t)N_NODES * HID];         // aggregated / activated (fp32)
__device__ float g_dinv[N_NODES];
__device__ int   g_deg[N_NODES];                       // zero at load; re-zeroed each run
__device__ int   g_rowptr[N_NODES + 1];
__device__ int   g_cursor[N_NODES];
__device__ int   g_csr[N_EDGES];
__device__ int   g_bsum[SCAN_NBLK];
__device__ int   g_boff[SCAN_NBLK];
__device__ unsigned int g_min[OUT_CH];

// ---------------- float <-> monotone uint key ------------------------------
__device__ __forceinline__ unsigned int fkey(float f) {
    unsigned int u = __float_as_uint(f);
    return (u & 0x80000000u) ? ~u : (u | 0x80000000u);
}
__device__ __forceinline__ float funkey(unsigned int k) {
    unsigned int u = (k & 0x80000000u) ? (k ^ 0x80000000u) : ~k;
    return __uint_as_float(u);
}

__device__ __forceinline__ uint32_t smem_u32(const void* p) {
    uint32_t a;
    asm("{ .reg .u64 t; cvta.to.shared.u64 t, %1; cvt.u32.u64 %0, t; }"
        : "=r"(a) : "l"(p));
    return a;
}

// unpack 8 bf16 (uint4) -> 8 floats via exact bit-shift widening
__device__ __forceinline__ void unpack8(uint4 v, float* f) {
    f[0] = __uint_as_float(v.x << 16);
    f[1] = __uint_as_float(v.x & 0xFFFF0000u);
    f[2] = __uint_as_float(v.y << 16);
    f[3] = __uint_as_float(v.y & 0xFFFF0000u);
    f[4] = __uint_as_float(v.z << 16);
    f[5] = __uint_as_float(v.z & 0xFFFF0000u);
    f[6] = __uint_as_float(v.w << 16);
    f[7] = __uint_as_float(v.w & 0xFFFF0000u);
}

// ---------------- CSR build ------------------------------------------------
__global__ void count_deg_kernel(const int* __restrict__ ei) {
    int e4 = (blockIdx.x * blockDim.x + threadIdx.x) * 4;
    if (e4 < N_EDGES) {
        int4 d = *reinterpret_cast<const int4*>(&ei[N_EDGES + e4]);
        atomicAdd(&g_deg[d.x], 1);
        atomicAdd(&g_deg[d.y], 1);
        atomicAdd(&g_deg[d.z], 1);
        atomicAdd(&g_deg[d.w], 1);
    }
}

__global__ void scan_pass1() {
    int i = blockIdx.x * 256 + threadIdx.x;
    int d = (i < N_NODES) ? g_deg[i] : 0;
    __shared__ int sm[256];
    sm[threadIdx.x] = d;
    __syncthreads();
#pragma unroll
    for (int o = 128; o > 0; o >>= 1) {
        if (threadIdx.x < o) sm[threadIdx.x] += sm[threadIdx.x + o];
        __syncthreads();
    }
    if (threadIdx.x == 0) g_bsum[blockIdx.x] = sm[0];
}

__global__ void scan_pass2() {
    __shared__ int sm[512];
    int t = threadIdx.x;
    if (t < OUT_CH) g_min[t] = 0xFFFFFFFFu;   // init fused-pool accumulator
    sm[t] = (t < SCAN_NBLK) ? g_bsum[t] : 0;
    __syncthreads();
    for (int o = 1; o < 512; o <<= 1) {
        int v = (t >= o) ? sm[t - o] : 0;
        __syncthreads();
        sm[t] += v;
        __syncthreads();
    }
    if (t < SCAN_NBLK) g_boff[t] = (t == 0) ? 0 : sm[t - 1];
    if (t == 511) g_rowptr[N_NODES] = sm[SCAN_NBLK - 1];
}

__global__ void scan_pass3() {
    int i = blockIdx.x * 256 + threadIdx.x;
    int d = (i < N_NODES) ? g_deg[i] : 0;
    __shared__ int sm[256];
    int t = threadIdx.x;
    sm[t] = d;
    __syncthreads();
    for (int o = 1; o < 256; o <<= 1) {
        int v = (t >= o) ? sm[t - o] : 0;
        __syncthreads();
        sm[t] += v;
        __syncthreads();
    }
    if (i < N_NODES) {
        int excl = g_boff[blockIdx.x] + sm[t] - d;
        g_rowptr[i] = excl;
        g_cursor[i] = excl;
        g_dinv[i] = rsqrtf((float)(d + 1));  // +1 self-loop
        g_deg[i] = 0;                        // restore zero invariant for next run
    }
}

__global__ void fill_csr_kernel(const int* __restrict__ ei) {
    int e4 = (blockIdx.x * blockDim.x + threadIdx.x) * 4;
    if (e4 < N_EDGES) {
        int4 s = *reinterpret_cast<const int4*>(&ei[e4]);
        int4 d = *reinterpret_cast<const int4*>(&ei[N_EDGES + e4]);
        g_csr[atomicAdd(&g_cursor[d.x], 1)] = s.x;
        g_csr[atomicAdd(&g_cursor[d.y], 1)] = s.y;
        g_csr[atomicAdd(&g_cursor[d.z], 1)] = s.z;
        g_csr[atomicAdd(&g_cursor[d.w], 1)] = s.w;
    }
}

// ---------------- tf32 mma helpers ------------------------------------------
__device__ __forceinline__ uint32_t f2tf32(float f) {
    uint32_t u;
    asm("cvt.rna.tf32.f32 %0, %1;" : "=r"(u) : "f"(f));
    return u;
}

__device__ __forceinline__ void mma_tf32(float* c, const uint32_t* a, const uint32_t* b) {
    asm volatile(
        "mma.sync.aligned.m16n8k8.row.col.f32.tf32.tf32.f32 "
        "{%0,%1,%2,%3}, {%4,%5,%6,%7}, {%8,%9}, {%0,%1,%2,%3};"
        : "+f"(c[0]), "+f"(c[1]), "+f"(c[2]), "+f"(c[3])
        : "r"(a[0]), "r"(a[1]), "r"(a[2]), "r"(a[3]), "r"(b[0]), "r"(b[1]));
}

// ---------------- persistent tensor-core GEMM (512 threads) ------------------
// outh[m][n] = bf16( scale(m) * (A @ W)[m][n] ), scale = g_dinv[m] if SCALE
// W resident in smem; A tiles (128x128 fp32) cp.async double-buffered.
template <int BN, bool SCALE>
__global__ void __launch_bounds__(512, 1)
gemm_persist_kernel(const float* __restrict__ A, const float* __restrict__ W,
                    __nv_bfloat16* __restrict__ outh, int M) {
    constexpr int PA = 132;
    constexpr int PB = BN + 8;
    constexpr int TN = BN / 32;
    const int ntiles = (M + 127) >> 7;

    extern __shared__ uint32_t smem[];
    uint32_t* Ws = smem;                                  // [128][PB] tf32
    float* Ab0 = reinterpret_cast<float*>(smem + 128 * PB);   // [128][PA] raw
    float* Ab1 = Ab0 + 128 * PA;

    const int tid = threadIdx.x;
    const int lane = tid & 31;
    const int wid = tid >> 5;
    const int wm = (wid & 3) * 32;
    const int wn = (wid >> 2) * (BN / 4);
    const int ar = lane >> 2;
    const int ak = lane & 3;
    const int bn = wn + ar;

    for (int i = tid; i < 128 * (BN / 4); i += 512) {
        int r = i / (BN / 4);
        int c4 = (i % (BN / 4)) * 4;
        float4 v = *reinterpret_cast<const float4*>(&W[(size_t)r * BN + c4]);
        uint4 u;
        u.x = f2tf32(v.x); u.y = f2tf32(v.y); u.z = f2tf32(v.z); u.w = f2tf32(v.w);
        *reinterpret_cast<uint4*>(&Ws[r * PB + c4]) = u;
    }

    const uint32_t ab_addr0 = smem_u32(Ab0);
    const uint32_t ab_addr1 = smem_u32(Ab1);

    auto issue_copy = [&](int buf, int tile) {
        const uint32_t base = buf ? ab_addr1 : ab_addr0;
        const int m0 = tile << 7;
#pragma unroll
        for (int t = 0; t < 8; t++) {
            int i = tid + t * 512;
            int r = i >> 5;
            int c4 = (i & 31) * 4;
            int row = m0 + r;
            uint32_t dst = base + (uint32_t)(r * PA + c4) * 4u;
            const float* src = &A[(size_t)(row < M ? row : 0) * 128 + c4];
            int sz = (row < M) ? 16 : 0;
            asm volatile("cp.async.cg.shared.global [%0], [%1], 16, %2;"
                         :: "r"(dst), "l"(src), "r"(sz) : "memory");
        }
        asm volatile("cp.async.commit_group;" ::: "memory");
    };

    int tile = blockIdx.x;
    int cur = 0;
    if (tile < ntiles) issue_copy(0, tile);

    for (; tile < ntiles; tile += gridDim.x) {
        const int next = tile + gridDim.x;
        asm volatile("cp.async.wait_group 0;" ::: "memory");
        __syncthreads();
        if (next < ntiles) issue_copy(cur ^ 1, next);

        const float* as = cur ? Ab1 : Ab0;
        float acc[2][TN][4] = {};

#pragma unroll
        for (int k0 = 0; k0 < 128; k0 += 8) {
            uint32_t a[2][4];
#pragma unroll
            for (int mi = 0; mi < 2; mi++) {
                int r = wm + mi * 16 + ar;
                a[mi][0] = f2tf32(as[r * PA + k0 + ak]);
                a[mi][1] = f2tf32(as[(r + 8) * PA + k0 + ak]);
                a[mi][2] = f2tf32(as[r * PA + k0 + ak + 4]);
                a[mi][3] = f2tf32(as[(r + 8) * PA + k0 + ak + 4]);
            }
            uint32_t b[TN][2];
#pragma unroll
            for (int ni = 0; ni < TN; ni++) {
                b[ni][0] = Ws[(k0 + ak) * PB + bn + ni * 8];
                b[ni][1] = Ws[(k0 + ak + 4) * PB + bn + ni * 8];
            }
#pragma unroll
            for (int mi = 0; mi < 2; mi++)
#pragma unroll
                for (int ni = 0; ni < TN; ni++)
                    mma_tf32(acc[mi][ni], a[mi], b[ni]);
        }

        const int m0t = tile << 7;
#pragma unroll
        for (int mi = 0; mi < 2; mi++) {
            int r0 = m0t + wm + mi * 16 + ar;
            int r1 = r0 + 8;
            float d0 = 1.f, d1 = 1.f;
            if (SCALE) {
                if (r0 < M) d0 = g_dinv[r0];
                if (r1 < M) d1 = g_dinv[r1];
            }
#pragma unroll
            for (int ni = 0; ni < TN; ni++) {
                int col = wn + ni * 8 + ak * 2;
                if (r0 < M) {
                    __nv_bfloat162 v0 =
                        __floats2bfloat162_rn(acc[mi][ni][0] * d0, acc[mi][ni][1] * d0);
                    *reinterpret_cast<__nv_bfloat162*>(&outh[(size_t)r0 * BN + col]) = v0;
                }
                if (r1 < M) {
                    __nv_bfloat162 v1 =
                        __floats2bfloat162_rn(acc[mi][ni][2] * d1, acc[mi][ni][3] * d1);
                    *reinterpret_cast<__nv_bfloat162*>(&outh[(size_t)r1 * BN + col]) = v1;
                }
            }
        }
        cur ^= 1;
    }
}

// ---------------- SpMM C=128: warp per node, half-warp per edge row ---------
// EDGE_SCALE (layer 1): h unscaled; apply dinv[src] per edge, dinv[gw] on self.
template <bool EDGE_SCALE>
__global__ void spmm128_kernel(const __nv_bfloat16* __restrict__ h,
                               const float* __restrict__ bias,
                               float* __restrict__ out) {
    int gw = (blockIdx.x * blockDim.x + threadIdx.x) >> 5;
    int lane = threadIdx.x & 31;
    if (gw >= N_NODES) return;
    const int half = lane >> 4;
    const int hl = lane & 15;
    const __nv_bfloat16* hp = h + hl * 8;   // per-lane base (saves addr IMADs)

    int beg = g_rowptr[gw];
    int end = g_rowptr[gw + 1];
    const float dv = g_dinv[gw];

    float acc[8];
    if (half == 0) {  // self loop on half 0
        uint4 v = *reinterpret_cast<const uint4*>(hp + (size_t)gw * 128);
        unpack8(v, acc);
        if (EDGE_SCALE) {
#pragma unroll
            for (int i = 0; i < 8; i++) acc[i] *= dv;
        }
    } else {
#pragma unroll
        for (int i = 0; i < 8; i++) acc[i] = 0.f;
    }

    int j = beg + half;
    for (; j + 2 < end; j += 4) {   // 2 edges per half in flight
        int s0 = g_csr[j];
        int s1 = g_csr[j + 2];
        uint4 v0 = *reinterpret_cast<const uint4*>(hp + (size_t)s0 * 128);
        uint4 v1 = *reinterpret_cast<const uint4*>(hp + (size_t)s1 * 128);
        float w0 = 1.f, w1 = 1.f;
        if (EDGE_SCALE) { w0 = g_dinv[s0]; w1 = g_dinv[s1]; }
        float f0[8], f1[8];
        unpack8(v0, f0);
        unpack8(v1, f1);
#pragma unroll
        for (int i = 0; i < 8; i++) acc[i] += w0 * f0[i] + w1 * f1[i];
    }
    if (j < end) {
        int s0 = g_csr[j];
        uint4 v0 = *reinterpret_cast<const uint4*>(hp + (size_t)s0 * 128);
        float w0 = 1.f;
        if (EDGE_SCALE) w0 = g_dinv[s0];
        float f0[8];
        unpack8(v0, f0);
#pragma unroll
        for (int i = 0; i < 8; i++) acc[i] += w0 * f0[i];
    }

    // combine halves
#pragma unroll
    for (int i = 0; i < 8; i++) acc[i] += __shfl_xor_sync(0xFFFFFFFFu, acc[i], 16);

    float o[8];
#pragma unroll
    for (int i = 0; i < 8; i++)
        o[i] = fmaxf(acc[i] * dv + bias[hl * 8 + i], 0.f);

    float4 v = (half == 0) ? make_float4(o[0], o[1], o[2], o[3])
                           : make_float4(o[4], o[5], o[6], o[7]);
    *reinterpret_cast<float4*>(&out[(size_t)gw * 128 + hl * 8 + half * 4]) = v;
}

// ---------------- SpMM C=64 fused with min pool (quarter-warp per edge) -----
__global__ void spmm_pool_kernel(const __nv_bfloat16* __restrict__ h,
                                 const float* __restrict__ bias) {
    __shared__ float spool[8 * 64];

    int wlocal = threadIdx.x >> 5;
    int gw = (blockIdx.x * blockDim.x + threadIdx.x) >> 5;
    int lane = threadIdx.x & 31;
    const int quarter = lane >> 3;
    const int ql = lane & 7;
    const __nv_bfloat16* hp = h + ql * 8;

    float o[8];
    if (gw < N_NODES) {
        int beg = g_rowptr[gw];
        int end = g_rowptr[gw + 1];

        float acc[8];
        if (quarter == 0) {  // self loop on quarter 0
            uint4 v = *reinterpret_cast<const uint4*>(hp + (size_t)gw * 64);
            unpack8(v, acc);
        } else {
#pragma unroll
            for (int i = 0; i < 8; i++) acc[i] = 0.f;
        }

        int j = beg + quarter;
        for (; j + 4 < end; j += 8) {   // 2 edges per quarter in flight
            int s0 = g_csr[j];
            int s1 = g_csr[j + 4];
            uint4 v0 = *reinterpret_cast<const uint4*>(hp + (size_t)s0 * 64);
            uint4 v1 = *reinterpret_cast<const uint4*>(hp + (size_t)s1 * 64);
            float f0[8], f1[8];
            unpack8(v0, f0);
            unpack8(v1, f1);
#pragma unroll
            for (int i = 0; i < 8; i++) acc[i] += f0[i] + f1[i];
        }
        if (j < end) {
            int s0 = g_csr[j];
            uint4 v0 = *reinterpret_cast<const uint4*>(hp + (size_t)s0 * 64);
            float f0[8];
            unpack8(v0, f0);
#pragma unroll
            for (int i = 0; i < 8; i++) acc[i] += f0[i];
        }

#pragma unroll
        for (int i = 0; i < 8; i++) acc[i] += __shfl_xor_sync(0xFFFFFFFFu, acc[i], 8);
#pragma unroll
        for (int i = 0; i < 8; i++) acc[i] += __shfl_xor_sync(0xFFFFFFFFu, acc[i], 16);

        float d = g_dinv[gw];
#pragma unroll
        for (int i = 0; i < 8; i++) o[i] = acc[i] * d + bias[ql * 8 + i];
    } else {
#pragma unroll
        for (int i = 0; i < 8; i++) o[i] = 3.4028235e38f;
    }

    if (lane < 8) {
#pragma unroll
        for (int i = 0; i < 8; i++) spool[wlocal * 64 + ql * 8 + i] = o[i];
    }
    __syncthreads();

    if (threadIdx.x < 64) {
        float m = spool[threadIdx.x];
#pragma unroll
        for (int w = 1; w < 8; w++) m = fminf(m, spool[w * 64 + threadIdx.x]);
        atomicMin(&g_min[threadIdx.x], fkey(m));
    }
}

__global__ void min_final_kernel(float* __restrict__ out) {
    out[threadIdx.x] = funkey(g_min[threadIdx.x]);
}

// ---------------- launch ----------------------------------------------------
extern "C" void kernel_launch(void* const* d_in, const int* in_sizes, int n_in,
                              void* d_out, int out_size) {
    const float* x  = (const float*)d_in[0];
    const int*   ei = (const int*)  d_in[1];
    const float* W1 = (const float*)d_in[2];
    const float* b1 = (const float*)d_in[3];
    const float* W2 = (const float*)d_in[4];
    const float* b2 = (const float*)d_in[5];
    const float* W3 = (const float*)d_in[6];
    const float* b3 = (const float*)d_in[7];
    float* out = (float*)d_out;

    __nv_bfloat16* h_ptr = nullptr;
    float* agg_ptr = nullptr;
    cudaGetSymbolAddress((void**)&h_ptr, g_hb);
    cudaGetSymbolAddress((void**)&agg_ptr, g_agg);

    const int SMEM_128 = (128 * 136 + 2 * 128 * 132) * 4;  // 204800 (200KB)
    const int SMEM_64  = (128 * 72 + 2 * 128 * 132) * 4;   // 172032 (168KB)
    cudaFuncSetAttribute((const void*)gemm_persist_kernel<128, false>,
                         cudaFuncAttributeMaxDynamicSharedMemorySize, SMEM_128);
    cudaFuncSetAttribute((const void*)gemm_persist_kernel<128, true>,
                         cudaFuncAttributeMaxDynamicSharedMemorySize, SMEM_128);
    cudaFuncSetAttribute((const void*)gemm_persist_kernel<64, true>,
                         cudaFuncAttributeMaxDynamicSharedMemorySize, SMEM_64);

    // side stream + events for CSR || GEMM1 overlap (created once; no device mem)
    static cudaStream_t s2 = nullptr;
    static cudaEvent_t e_fork = nullptr, e_join = nullptr;
    if (s2 == nullptr) {
        cudaStreamCreateWithFlags(&s2, cudaStreamNonBlocking);
        cudaEventCreateWithFlags(&e_fork, cudaEventDisableTiming);
        cudaEventCreateWithFlags(&e_join, cudaEventDisableTiming);
    }

    const int TPB = 256;
    const int GEMM_GRID = 148;   // persistent: 1 CTA/SM
    const int spmm_blocks = (N_NODES * 32 + TPB - 1) / TPB;

    // ---- fork: GEMM1 (x@W1, scale-free) on side stream -----------------------
    cudaEventRecord(e_fork, 0);
    cudaStreamWaitEvent(s2, e_fork, 0);
    gemm_persist_kernel<128, false><<<GEMM_GRID, 512, SMEM_128, s2>>>(x, W1, h_ptr, N_NODES);
    cudaEventRecord(e_join, s2);

    // ---- CSR build chain on main stream (independent of GEMM1) ---------------
    count_deg_kernel<<<(N_EDGES / 4 + TPB - 1) / TPB, TPB>>>(ei);
    scan_pass1<<<SCAN_NBLK, 256>>>();
    scan_pass2<<<1, 512>>>();
    scan_pass3<<<SCAN_NBLK, 256>>>();
    fill_csr_kernel<<<(N_EDGES / 4 + TPB - 1) / TPB, TPB>>>(ei);

    // ---- join: spmm1 needs both GEMM1 output and CSR --------------------------
    cudaStreamWaitEvent(0, e_join, 0);
    spmm128_kernel<true><<<spmm_blocks, TPB>>>(h_ptr, b1, agg_ptr);

    // Layer 2
    gemm_persist_kernel<128, true><<<GEMM_GRID, 512, SMEM_128>>>(agg_ptr, W2, h_ptr, N_NODES);
    spmm128_kernel<false><<<spmm_blocks, TPB>>>(h_ptr, b2, agg_ptr);

    // Layer 3 (64 ch) fused with min pool
    gemm_persist_kernel<64, true><<<GEMM_GRID, 512, SMEM_64>>>(agg_ptr, W3, h_ptr, N_NODES);
    spmm_pool_kernel<<<spmm_blocks, TPB>>>(h_ptr, b3);

    min_final_kernel<<<1, 64>>>(out);
}

// round 17
// speedup vs baseline: 1.0449x; 1.0171x over previous
#include <cuda_runtime.h>
#include <cuda_bf16.h>
#include <math.h>
#include <cstdint>

#define N_NODES 100000
#define N_EDGES 1600000
#define IN_CH   128
#define HID     128
#define OUT_CH  64

#define SCAN_NBLK ((N_NODES + 255) / 256)   // 391

// ---------------- scratch (device globals; no allocation allowed) ----------
__device__ __nv_bfloat16 g_hb[(size_t)N_NODES * HID];  // transformed features (bf16)
__device__ float g_agg[(size_t)N_NODES * HID];         // aggregated / activated (fp32)
__device__ float g_dinv[N_NODES];
__device__ int   g_deg[N_NODES];                       // zero at load; re-zeroed each run
__device__ int   g_rowptr[N_NODES + 1];
__device__ int   g_cursor[N_NODES];
__device__ int   g_csr[N_EDGES];
__device__ int   g_bsum[SCAN_NBLK];
__device__ int   g_boff[SCAN_NBLK];
__device__ unsigned int g_min[OUT_CH];

// ---------------- float <-> monotone uint key ------------------------------
__device__ __forceinline__ unsigned int fkey(float f) {
    unsigned int u = __float_as_uint(f);
    return (u & 0x80000000u) ? ~u : (u | 0x80000000u);
}
__device__ __forceinline__ float funkey(unsigned int k) {
    unsigned int u = (k & 0x80000000u) ? (k ^ 0x80000000u) : ~k;
    return __uint_as_float(u);
}

__device__ __forceinline__ uint32_t smem_u32(const void* p) {
    uint32_t a;
    asm("{ .reg .u64 t; cvta.to.shared.u64 t, %1; cvt.u32.u64 %0, t; }"
        : "=r"(a) : "l"(p));
    return a;
}

// unpack 8 bf16 (uint4) -> 8 floats via exact bit-shift widening
__device__ __forceinline__ void unpack8(uint4 v, float* f) {
    f[0] = __uint_as_float(v.x << 16);
    f[1] = __uint_as_float(v.x & 0xFFFF0000u);
    f[2] = __uint_as_float(v.y << 16);
    f[3] = __uint_as_float(v.y & 0xFFFF0000u);
    f[4] = __uint_as_float(v.z << 16);
    f[5] = __uint_as_float(v.z & 0xFFFF0000u);
    f[6] = __uint_as_float(v.w << 16);
    f[7] = __uint_as_float(v.w & 0xFFFF0000u);
}

// ---------------- CSR build ------------------------------------------------
__global__ void count_deg_kernel(const int* __restrict__ ei) {
    int e4 = (blockIdx.x * blockDim.x + threadIdx.x) * 4;
    if (e4 < N_EDGES) {
        int4 d = *reinterpret_cast<const int4*>(&ei[N_EDGES + e4]);
        atomicAdd(&g_deg[d.x], 1);
        atomicAdd(&g_deg[d.y], 1);
        atomicAdd(&g_deg[d.z], 1);
        atomicAdd(&g_deg[d.w], 1);
    }
}

__global__ void scan_pass1() {
    int i = blockIdx.x * 256 + threadIdx.x;
    int d = (i < N_NODES) ? g_deg[i] : 0;
    __shared__ int sm[256];
    sm[threadIdx.x] = d;
    __syncthreads();
#pragma unroll
    for (int o = 128; o > 0; o >>= 1) {
        if (threadIdx.x < o) sm[threadIdx.x] += sm[threadIdx.x + o];
        __syncthreads();
    }
    if (threadIdx.x == 0) g_bsum[blockIdx.x] = sm[0];
}

__global__ void scan_pass2() {
    __shared__ int sm[512];
    int t = threadIdx.x;
    if (t < OUT_CH) g_min[t] = 0xFFFFFFFFu;   // init fused-pool accumulator
    sm[t] = (t < SCAN_NBLK) ? g_bsum[t] : 0;
    __syncthreads();
    for (int o = 1; o < 512; o <<= 1) {
        int v = (t >= o) ? sm[t - o] : 0;
        __syncthreads();
        sm[t] += v;
        __syncthreads();
    }
    if (t < SCAN_NBLK) g_boff[t] = (t == 0) ? 0 : sm[t - 1];
    if (t == 511) g_rowptr[N_NODES] = sm[SCAN_NBLK - 1];
}

__global__ void scan_pass3() {
    int i = blockIdx.x * 256 + threadIdx.x;
    int d = (i < N_NODES) ? g_deg[i] : 0;
    __shared__ int sm[256];
    int t = threadIdx.x;
    sm[t] = d;
    __syncthreads();
    for (int o = 1; o < 256; o <<= 1) {
        int v = (t >= o) ? sm[t - o] : 0;
        __syncthreads();
        sm[t] += v;
        __syncthreads();
    }
    if (i < N_NODES) {
        int excl = g_boff[blockIdx.x] + sm[t] - d;
        g_rowptr[i] = excl;
        g_cursor[i] = excl;
        g_dinv[i] = rsqrtf((float)(d + 1));  // +1 self-loop
        g_deg[i] = 0;                        // restore zero invariant for next run
    }
}

__global__ void fill_csr_kernel(const int* __restrict__ ei) {
    int e4 = (blockIdx.x * blockDim.x + threadIdx.x) * 4;
    if (e4 < N_EDGES) {
        int4 s = *reinterpret_cast<const int4*>(&ei[e4]);
        int4 d = *reinterpret_cast<const int4*>(&ei[N_EDGES + e4]);
        g_csr[atomicAdd(&g_cursor[d.x], 1)] = s.x;
        g_csr[atomicAdd(&g_cursor[d.y], 1)] = s.y;
        g_csr[atomicAdd(&g_cursor[d.z], 1)] = s.z;
        g_csr[atomicAdd(&g_cursor[d.w], 1)] = s.w;
    }
}

// ---------------- tf32 mma helpers ------------------------------------------
__device__ __forceinline__ uint32_t f2tf32(float f) {
    uint32_t u;
    asm("cvt.rna.tf32.f32 %0, %1;" : "=r"(u) : "f"(f));
    return u;
}

__device__ __forceinline__ void mma_tf32(float* c, const uint32_t* a, const uint32_t* b) {
    asm volatile(
        "mma.sync.aligned.m16n8k8.row.col.f32.tf32.tf32.f32 "
        "{%0,%1,%2,%3}, {%4,%5,%6,%7}, {%8,%9}, {%0,%1,%2,%3};"
        : "+f"(c[0]), "+f"(c[1]), "+f"(c[2]), "+f"(c[3])
        : "r"(a[0]), "r"(a[1]), "r"(a[2]), "r"(a[3]), "r"(b[0]), "r"(b[1]));
}

// ---------------- persistent tensor-core GEMM (512 threads) ------------------
// outh[m][n] = bf16( scale(m) * (A @ W)[m][n] ), scale = g_dinv[m] if SCALE
// W resident in smem as k-PAIRED uint2 {tf32 W[k][n], tf32 W[k+4][n]} so the
// B fragment is ONE LDS.64 per n8-tile (4 LDS.64 replace 8 LDS.32 per k-step).
// A tiles (128x128 fp32) cp.async double-buffered; cvt.rna in-register.
template <int BN, bool SCALE>
__global__ void __launch_bounds__(512, 1)
gemm_persist_kernel(const float* __restrict__ A, const float* __restrict__ W,
                    __nv_bfloat16* __restrict__ outh, int M) {
    constexpr int PA = 132;
    constexpr int PW2 = BN + 4;      // pair pitch: (BN+4)*8B ≡ 32 mod 128 (conflict-free)
    constexpr int TN = BN / 32;
    const int ntiles = (M + 127) >> 7;

    extern __shared__ uint32_t smem[];
    uint2* W2s = reinterpret_cast<uint2*>(smem);              // [64][PW2] pairs
    float* Ab0 = reinterpret_cast<float*>(smem + 2 * 64 * PW2);   // [128][PA] raw
    float* Ab1 = Ab0 + 128 * PA;

    const int tid = threadIdx.x;
    const int lane = tid & 31;
    const int wid = tid >> 5;
    const int wm = (wid & 3) * 32;
    const int wn = (wid >> 2) * (BN / 4);
    const int ar = lane >> 2;
    const int ak = lane & 3;
    const int bn = wn + ar;

    // ---- load W once as tf32 k-pairs: pr = g*4+ak' -> rows {8g+ak', 8g+ak'+4}
    for (int i = tid; i < 64 * (BN / 4); i += 512) {
        int pr = i / (BN / 4);
        int c4 = (i % (BN / 4)) * 4;
        int k1 = ((pr >> 2) << 3) + (pr & 3);   // 8g + ak'
        float4 v0 = *reinterpret_cast<const float4*>(&W[(size_t)k1 * BN + c4]);
        float4 v1 = *reinterpret_cast<const float4*>(&W[(size_t)(k1 + 4) * BN + c4]);
        uint2* dst = &W2s[pr * PW2 + c4];
        dst[0] = make_uint2(f2tf32(v0.x), f2tf32(v1.x));
        dst[1] = make_uint2(f2tf32(v0.y), f2tf32(v1.y));
        dst[2] = make_uint2(f2tf32(v0.z), f2tf32(v1.z));
        dst[3] = make_uint2(f2tf32(v0.w), f2tf32(v1.w));
    }

    const uint32_t ab_addr0 = smem_u32(Ab0);
    const uint32_t ab_addr1 = smem_u32(Ab1);

    auto issue_copy = [&](int buf, int tile) {
        const uint32_t base = buf ? ab_addr1 : ab_addr0;
        const int m0 = tile << 7;
#pragma unroll
        for (int t = 0; t < 8; t++) {
            int i = tid + t * 512;
            int r = i >> 5;
            int c4 = (i & 31) * 4;
            int row = m0 + r;
            uint32_t dst = base + (uint32_t)(r * PA + c4) * 4u;
            const float* src = &A[(size_t)(row < M ? row : 0) * 128 + c4];
            int sz = (row < M) ? 16 : 0;
            asm volatile("cp.async.cg.shared.global [%0], [%1], 16, %2;"
                         :: "r"(dst), "l"(src), "r"(sz) : "memory");
        }
        asm volatile("cp.async.commit_group;" ::: "memory");
    };

    int tile = blockIdx.x;
    int cur = 0;
    if (tile < ntiles) issue_copy(0, tile);

    for (; tile < ntiles; tile += gridDim.x) {
        const int next = tile + gridDim.x;
        asm volatile("cp.async.wait_group 0;" ::: "memory");
        __syncthreads();
        if (next < ntiles) issue_copy(cur ^ 1, next);

        const float* as = cur ? Ab1 : Ab0;
        float acc[2][TN][4] = {};

#pragma unroll
        for (int k0 = 0; k0 < 128; k0 += 8) {
            uint32_t a[2][4];
#pragma unroll
            for (int mi = 0; mi < 2; mi++) {
                int r = wm + mi * 16 + ar;
                a[mi][0] = f2tf32(as[r * PA + k0 + ak]);
                a[mi][1] = f2tf32(as[(r + 8) * PA + k0 + ak]);
                a[mi][2] = f2tf32(as[r * PA + k0 + ak + 4]);
                a[mi][3] = f2tf32(as[(r + 8) * PA + k0 + ak + 4]);
            }
            // pair-row pr = (k0/8)*4 + ak = k0/2 + ak
            const uint2* wrow = &W2s[((k0 >> 1) + ak) * PW2 + bn];
            uint32_t b[TN][2];
#pragma unroll
            for (int ni = 0; ni < TN; ni++) {
                uint2 p = wrow[ni * 8];
                b[ni][0] = p.x;
                b[ni][1] = p.y;
            }
#pragma unroll
            for (int mi = 0; mi < 2; mi++)
#pragma unroll
                for (int ni = 0; ni < TN; ni++)
                    mma_tf32(acc[mi][ni], a[mi], b[ni]);
        }

        const int m0t = tile << 7;
#pragma unroll
        for (int mi = 0; mi < 2; mi++) {
            int r0 = m0t + wm + mi * 16 + ar;
            int r1 = r0 + 8;
            float d0 = 1.f, d1 = 1.f;
            if (SCALE) {
                if (r0 < M) d0 = g_dinv[r0];
                if (r1 < M) d1 = g_dinv[r1];
            }
#pragma unroll
            for (int ni = 0; ni < TN; ni++) {
                int col = wn + ni * 8 + ak * 2;
                if (r0 < M) {
                    __nv_bfloat162 v0 =
                        __floats2bfloat162_rn(acc[mi][ni][0] * d0, acc[mi][ni][1] * d0);
                    *reinterpret_cast<__nv_bfloat162*>(&outh[(size_t)r0 * BN + col]) = v0;
                }
                if (r1 < M) {
                    __nv_bfloat162 v1 =
                        __floats2bfloat162_rn(acc[mi][ni][2] * d1, acc[mi][ni][3] * d1);
                    *reinterpret_cast<__nv_bfloat162*>(&outh[(size_t)r1 * BN + col]) = v1;
                }
            }
        }
        cur ^= 1;
    }
}

// ---------------- SpMM C=128: warp per node, half-warp per edge row ---------
// EDGE_SCALE (layer 1): h unscaled; apply dinv[src] per edge, dinv[gw] on self.
template <bool EDGE_SCALE>
__global__ void spmm128_kernel(const __nv_bfloat16* __restrict__ h,
                               const float* __restrict__ bias,
                               float* __restrict__ out) {
    int gw = (blockIdx.x * blockDim.x + threadIdx.x) >> 5;
    int lane = threadIdx.x & 31;
    if (gw >= N_NODES) return;
    const int half = lane >> 4;
    const int hl = lane & 15;
    const __nv_bfloat16* hp = h + hl * 8;

    int beg = g_rowptr[gw];
    int end = g_rowptr[gw + 1];
    const float dv = g_dinv[gw];

    float acc[8];
    if (half == 0) {  // self loop on half 0
        uint4 v = *reinterpret_cast<const uint4*>(hp + (size_t)gw * 128);
        unpack8(v, acc);
        if (EDGE_SCALE) {
#pragma unroll
            for (int i = 0; i < 8; i++) acc[i] *= dv;
        }
    } else {
#pragma unroll
        for (int i = 0; i < 8; i++) acc[i] = 0.f;
    }

    int j = beg + half;
    for (; j + 6 < end; j += 8) {   // 4 edge rows in flight per half-warp
        int s0 = g_csr[j];
        int s1 = g_csr[j + 2];
        int s2 = g_csr[j + 4];
        int s3 = g_csr[j + 6];
        uint4 v0 = *reinterpret_cast<const uint4*>(hp + (size_t)s0 * 128);
        uint4 v1 = *reinterpret_cast<const uint4*>(hp + (size_t)s1 * 128);
        uint4 v2 = *reinterpret_cast<const uint4*>(hp + (size_t)s2 * 128);
        uint4 v3 = *reinterpret_cast<const uint4*>(hp + (size_t)s3 * 128);
        float w0 = 1.f, w1 = 1.f, w2 = 1.f, w3 = 1.f;
        if (EDGE_SCALE) {
            w0 = g_dinv[s0]; w1 = g_dinv[s1]; w2 = g_dinv[s2]; w3 = g_dinv[s3];
        }
        float f0[8], f1[8], f2[8], f3[8];
        unpack8(v0, f0); unpack8(v1, f1); unpack8(v2, f2); unpack8(v3, f3);
#pragma unroll
        for (int i = 0; i < 8; i++)
            acc[i] += (w0 * f0[i] + w1 * f1[i]) + (w2 * f2[i] + w3 * f3[i]);
    }
    for (; j + 2 < end; j += 4) {   // 2 edges per half
        int s0 = g_csr[j];
        int s1 = g_csr[j + 2];
        uint4 v0 = *reinterpret_cast<const uint4*>(hp + (size_t)s0 * 128);
        uint4 v1 = *reinterpret_cast<const uint4*>(hp + (size_t)s1 * 128);
        float w0 = 1.f, w1 = 1.f;
        if (EDGE_SCALE) { w0 = g_dinv[s0]; w1 = g_dinv[s1]; }
        float f0[8], f1[8];
        unpack8(v0, f0);
        unpack8(v1, f1);
#pragma unroll
        for (int i = 0; i < 8; i++) acc[i] += w0 * f0[i] + w1 * f1[i];
    }
    if (j < end) {
        int s0 = g_csr[j];
        uint4 v0 = *reinterpret_cast<const uint4*>(hp + (size_t)s0 * 128);
        float w0 = 1.f;
        if (EDGE_SCALE) w0 = g_dinv[s0];
        float f0[8];
        unpack8(v0, f0);
#pragma unroll
        for (int i = 0; i < 8; i++) acc[i] += w0 * f0[i];
    }

    // combine halves
#pragma unroll
    for (int i = 0; i < 8; i++) acc[i] += __shfl_xor_sync(0xFFFFFFFFu, acc[i], 16);

    float o[8];
#pragma unroll
    for (int i = 0; i < 8; i++)
        o[i] = fmaxf(acc[i] * dv + bias[hl * 8 + i], 0.f);

    float4 v = (half == 0) ? make_float4(o[0], o[1], o[2], o[3])
                           : make_float4(o[4], o[5], o[6], o[7]);
    *reinterpret_cast<float4*>(&out[(size_t)gw * 128 + hl * 8 + half * 4]) = v;
}

// ---------------- SpMM C=64 fused with min pool (quarter-warp per edge) -----
__global__ void spmm_pool_kernel(const __nv_bfloat16* __restrict__ h,
                                 const float* __restrict__ bias) {
    __shared__ float spool[8 * 64];

    int wlocal = threadIdx.x >> 5;
    int gw = (blockIdx.x * blockDim.x + threadIdx.x) >> 5;
    int lane = threadIdx.x & 31;
    const int quarter = lane >> 3;
    const int ql = lane & 7;
    const __nv_bfloat16* hp = h + ql * 8;

    float o[8];
    if (gw < N_NODES) {
        int beg = g_rowptr[gw];
        int end = g_rowptr[gw + 1];

        float acc[8];
        if (quarter == 0) {  // self loop on quarter 0
            uint4 v = *reinterpret_cast<const uint4*>(hp + (size_t)gw * 64);
            unpack8(v, acc);
        } else {
#pragma unroll
            for (int i = 0; i < 8; i++) acc[i] = 0.f;
        }

        int j = beg + quarter;
        for (; j + 4 < end; j += 8) {   // 2 edges per quarter in flight
            int s0 = g_csr[j];
            int s1 = g_csr[j + 4];
            uint4 v0 = *reinterpret_cast<const uint4*>(hp + (size_t)s0 * 64);
            uint4 v1 = *reinterpret_cast<const uint4*>(hp + (size_t)s1 * 64);
            float f0[8], f1[8];
            unpack8(v0, f0);
            unpack8(v1, f1);
#pragma unroll
            for (int i = 0; i < 8; i++) acc[i] += f0[i] + f1[i];
        }
        if (j < end) {
            int s0 = g_csr[j];
            uint4 v0 = *reinterpret_cast<const uint4*>(hp + (size_t)s0 * 64);
            float f0[8];
            unpack8(v0, f0);
#pragma unroll
            for (int i = 0; i < 8; i++) acc[i] += f0[i];
        }

#pragma unroll
        for (int i = 0; i < 8; i++) acc[i] += __shfl_xor_sync(0xFFFFFFFFu, acc[i], 8);
#pragma unroll
        for (int i = 0; i < 8; i++) acc[i] += __shfl_xor_sync(0xFFFFFFFFu, acc[i], 16);

        float d = g_dinv[gw];
#pragma unroll
        for (int i = 0; i < 8; i++) o[i] = acc[i] * d + bias[ql * 8 + i];
    } else {
#pragma unroll
        for (int i = 0; i < 8; i++) o[i] = 3.4028235e38f;
    }

    if (lane < 8) {
#pragma unroll
        for (int i = 0; i < 8; i++) spool[wlocal * 64 + ql * 8 + i] = o[i];
    }
    __syncthreads();

    if (threadIdx.x < 64) {
        float m = spool[threadIdx.x];
#pragma unroll
        for (int w = 1; w < 8; w++) m = fminf(m, spool[w * 64 + threadIdx.x]);
        atomicMin(&g_min[threadIdx.x], fkey(m));
    }
}

__global__ void min_final_kernel(float* __restrict__ out) {
    out[threadIdx.x] = funkey(g_min[threadIdx.x]);
}

// ---------------- launch ----------------------------------------------------
extern "C" void kernel_launch(void* const* d_in, const int* in_sizes, int n_in,
                              void* d_out, int out_size) {
    const float* x  = (const float*)d_in[0];
    const int*   ei = (const int*)  d_in[1];
    const float* W1 = (const float*)d_in[2];
    const float* b1 = (const float*)d_in[3];
    const float* W2 = (const float*)d_in[4];
    const float* b2 = (const float*)d_in[5];
    const float* W3 = (const float*)d_in[6];
    const float* b3 = (const float*)d_in[7];
    float* out = (float*)d_out;

    __nv_bfloat16* h_ptr = nullptr;
    float* agg_ptr = nullptr;
    cudaGetSymbolAddress((void**)&h_ptr, g_hb);
    cudaGetSymbolAddress((void**)&agg_ptr, g_agg);

    // smem: W pairs (64 x (BN+4) x 8B) + 2 A buffers (128 x 132 x 4B)
    const int SMEM_128 = 64 * 132 * 8 + 2 * 128 * 132 * 4;  // 67584 + 135168 = 202752
    const int SMEM_64  = 64 * 68 * 8 + 2 * 128 * 132 * 4;   // 34816 + 135168 = 169984
    cudaFuncSetAttribute((const void*)gemm_persist_kernel<128, false>,
                         cudaFuncAttributeMaxDynamicSharedMemorySize, SMEM_128);
    cudaFuncSetAttribute((const void*)gemm_persist_kernel<128, true>,
                         cudaFuncAttributeMaxDynamicSharedMemorySize, SMEM_128);
    cudaFuncSetAttribute((const void*)gemm_persist_kernel<64, true>,
                         cudaFuncAttributeMaxDynamicSharedMemorySize, SMEM_64);

    // side stream + events for CSR || GEMM1 overlap (neutral but harmless)
    static cudaStream_t s2 = nullptr;
    static cudaEvent_t e_fork = nullptr, e_join = nullptr;
    if (s2 == nullptr) {
        cudaStreamCreateWithFlags(&s2, cudaStreamNonBlocking);
        cudaEventCreateWithFlags(&e_fork, cudaEventDisableTiming);
        cudaEventCreateWithFlags(&e_join, cudaEventDisableTiming);
    }

    const int TPB = 256;
    const int GEMM_GRID = 148;   // persistent: 1 CTA/SM
    const int spmm_blocks = (N_NODES * 32 + TPB - 1) / TPB;

    // ---- fork: GEMM1 (x@W1, scale-free) on side stream -----------------------
    cudaEventRecord(e_fork, 0);
    cudaStreamWaitEvent(s2, e_fork, 0);
    gemm_persist_kernel<128, false><<<GEMM_GRID, 512, SMEM_128, s2>>>(x, W1, h_ptr, N_NODES);
    cudaEventRecord(e_join, s2);

    // ---- CSR build chain on main stream (independent of GEMM1) ---------------
    count_deg_kernel<<<(N_EDGES / 4 + TPB - 1) / TPB, TPB>>>(ei);
    scan_pass1<<<SCAN_NBLK, 256>>>();
    scan_pass2<<<1, 512>>>();
    scan_pass3<<<SCAN_NBLK, 256>>>();
    fill_csr_kernel<<<(N_EDGES / 4 + TPB - 1) / TPB, TPB>>>(ei);

    // ---- join: spmm1 needs both GEMM1 output and CSR --------------------------
    cudaStreamWaitEvent(0, e_join, 0);
    spmm128_kernel<true><<<spmm_blocks, TPB>>>(h_ptr, b1, agg_ptr);

    // Layer 2
    gemm_persist_kernel<128, true><<<GEMM_GRID, 512, SMEM_128>>>(agg_ptr, W2, h_ptr, N_NODES);
    spmm128_kernel<false><<<spmm_blocks, TPB>>>(h_ptr, b2, agg_ptr);

    // Layer 3 (64 ch) fused with min pool
    gemm_persist_kernel<64, true><<<GEMM_GRID, 512, SMEM_64>>>(agg_ptr, W3, h_ptr, N_NODES);
    spmm_pool_kernel<<<spmm_blocks, TPB>>>(h_ptr, b3);

    min_final_kernel<<<1, 64>>>(out);
}